// round 5
// baseline (speedup 1.0000x reference)
#include <cuda_runtime.h>
#include <cstdint>
#include <cstddef>

// L1 attention: out[b,s,t,h] = -(1/sqrt(D)) * sum_d |q[b,s,h,d] - k[b,t,h,d]|
// B=2, S=2048, H=8, D=32. Output [b,s,t,h].
//
// Compute floor: 1 alu op (LOP3 abs-half) + 1 fma op (FADD2-half) per element.
// Inner unit per d-pair (u64): add.rn.f32x2 (fma) + 64-bit AND (2x LOP3, alu)
// + add.rn.f32x2 (fma). -k stored in SMEM so diff is a single packed add.
//
// This round vs R2 (207us): LDS.128 tiles (ulonglong2 = 2 d-pairs per load,
// halves shared-load slots) and 3 CTAs/SM (2s x 8t x h per thread -> 32 acc
// regs instead of 64; __launch_bounds__(256,3) -> 24 warps/SM for latency
// hiding; R2 had only 16 and issue=68.6%).

namespace {
constexpr int Bc  = 2;
constexpr int Sc  = 2048;
constexpr int Hc  = 8;
constexpr int Dc  = 32;
constexpr int SB  = 16;              // s rows per block
constexpr int TB  = 32;              // t cols per block
constexpr int NQ  = 8;               // 16B chunks per (s,h) row (32 floats)
constexpr int QROWS = SB * Hc;       // 128
constexpr int KROWS = TB * Hc;       // 256
constexpr int QST = QROWS + 1;       // 129, padded stride in 16B units
constexpr int KST = KROWS + 1;       // 257
constexpr int SMEM_U128 = NQ * QST + NQ * KST;   // 1032 + 2056 = 3088
}

__global__ void __launch_bounds__(256, 3)
l1attn_kernel(const float* __restrict__ qg_, const float* __restrict__ kg_,
              float* __restrict__ out) {
    extern __shared__ ulonglong2 sm[];
    ulonglong2* qs = sm;               // [NQ][QST]
    ulonglong2* ks = sm + NQ * QST;    // [NQ][KST]  (negated k)

    const int tid = threadIdx.x;
    const int b   = blockIdx.z;
    const int s0  = blockIdx.y * SB;
    const int t0  = blockIdx.x * TB;

    const float4* qg = reinterpret_cast<const float4*>(qg_ + (size_t)(b * Sc + s0) * Hc * Dc);
    const float4* kg = reinterpret_cast<const float4*>(kg_ + (size_t)(b * Sc + t0) * Hc * Dc);

    // Fill q tile: 1024 float4, 4/thread. g = row*8 + c -> transposed [c][row].
    #pragma unroll
    for (int i = 0; i < (QROWS * NQ) / 256; i++) {
        int g = tid + i * 256;
        int r = g >> 3;
        int c = g & 7;
        float4 v = qg[g];
        reinterpret_cast<float4&>(qs[c * QST + r]) = v;
    }
    // Fill k tile negated: 2048 float4, 8/thread.
    #pragma unroll
    for (int i = 0; i < (KROWS * NQ) / 256; i++) {
        int g = tid + i * 256;
        int r = g >> 3;
        int c = g & 7;
        float4 w = kg[g];
        w.x = -w.x; w.y = -w.y; w.z = -w.z; w.w = -w.w;
        reinterpret_cast<float4&>(ks[c * KST + r]) = w;
    }
    __syncthreads();

    // Mapping: h = tid&7, tq = (tid>>3)&3, warp sw = tid>>5 (0..7).
    // Thread tile: 2 s (sw + 8*ii) x 8 t (tq + 4*jj), fixed h.
    const int h  = tid & 7;
    const int tq = (tid >> 3) & 3;
    const int sw = tid >> 5;
    const int qoff = sw * 8 + h;     // + 64*ii   (16B-unit row index, < 128)
    const int koff = tq * 8 + h;     // + 32*jj

    unsigned long long acc[2][8];
    #pragma unroll
    for (int ii = 0; ii < 2; ii++)
        #pragma unroll
        for (int jj = 0; jj < 8; jj++)
            acc[ii][jj] = 0ull;

    #pragma unroll
    for (int c = 0; c < NQ; c++) {            // each c = 4 d's (2 packed pairs)
        const ulonglong2* qrow = qs + c * QST;
        const ulonglong2* krow = ks + c * KST;
        ulonglong2 q2[2];
        #pragma unroll
        for (int ii = 0; ii < 2; ii++) q2[ii] = qrow[qoff + 64 * ii];

        #pragma unroll
        for (int half = 0; half < 2; half++) {     // split k fringe: lower reg peak
            ulonglong2 k2[4];
            #pragma unroll
            for (int j = 0; j < 4; j++) k2[j] = krow[koff + 32 * (half * 4 + j)];
            #pragma unroll
            for (int ii = 0; ii < 2; ii++) {
                #pragma unroll
                for (int j = 0; j < 4; j++) {
                    int jj = half * 4 + j;
                    unsigned long long d2, a;
                    asm("add.rn.f32x2 %0, %1, %2;" : "=l"(d2) : "l"(q2[ii].x), "l"(k2[j].x));
                    d2 &= 0x7FFFFFFF7FFFFFFFULL;
                    asm("add.rn.f32x2 %0, %1, %2;" : "=l"(a) : "l"(acc[ii][jj]), "l"(d2));
                    acc[ii][jj] = a;
                    asm("add.rn.f32x2 %0, %1, %2;" : "=l"(d2) : "l"(q2[ii].y), "l"(k2[j].y));
                    d2 &= 0x7FFFFFFF7FFFFFFFULL;
                    asm("add.rn.f32x2 %0, %1, %2;" : "=l"(a) : "l"(acc[ii][jj]), "l"(d2));
                    acc[ii][jj] = a;
                }
            }
        }
    }

    // Epilogue: 16 STG.32, contiguous 128B per warp over (t,h).
    const float nscale = -0.17677669529663687f;  // -1/sqrt(32)
    #pragma unroll
    for (int ii = 0; ii < 2; ii++) {
        int s = s0 + sw + 8 * ii;
        size_t rowbase = ((size_t)b * Sc + s) * (size_t)Sc;
        #pragma unroll
        for (int jj = 0; jj < 8; jj++) {
            int t = t0 + tq + 4 * jj;
            float2 a = reinterpret_cast<float2&>(acc[ii][jj]);
            out[(rowbase + t) * Hc + h] = (a.x + a.y) * nscale;
        }
    }
}

extern "C" void kernel_launch(void* const* d_in, const int* in_sizes, int n_in,
                              void* d_out, int out_size) {
    const float* q = (const float*)d_in[0];
    const float* k = (const float*)d_in[1];
    float* out = (float*)d_out;

    const int smem_bytes = SMEM_U128 * (int)sizeof(ulonglong2);  // 49408
    cudaFuncSetAttribute(l1attn_kernel,
                         cudaFuncAttributeMaxDynamicSharedMemorySize, smem_bytes);

    dim3 grid(Sc / TB, Sc / SB, Bc);   // (64, 128, 2)
    l1attn_kernel<<<grid, 256, smem_bytes>>>(q, k, out);
}

// round 6
// speedup vs baseline: 1.0587x; 1.0587x over previous
#include <cuda_runtime.h>
#include <cstdint>
#include <cstddef>

// L1 attention: out[b,s,t,h] = -(1/sqrt(D)) * sum_d |q[b,s,h,d] - k[b,t,h,d]|
// B=2, S=2048, H=8, D=32. Output [b,s,t,h].
//
// Inner unit per packed d-pair: add.rn.f32x2 (fma) + 64-bit AND = 2x LOP3
// (alu) + add.rn.f32x2 (fma). -k stored in SMEM so diff is one packed add.
// Pipes balanced 2+2 slots per 2 elements -> ~119us floor; issue efficiency
// is the battle.
//
// R6 vs R2(207us)/R5(219us): crossbar model says bytes/element is what
// matters (R5 saturated it at 106% of fma time). Tile 32s x 16t, per-thread
// 4s x 4t -> 32 acc regs + 32 fringe regs => 3 CTAs/SM (24 warps, 6/SMSP)
// for latency hiding, while crossbar stays at ~62% of fma time and LDS issue
// overhead is 6%.

namespace {
constexpr int Bc  = 2;
constexpr int Sc  = 2048;
constexpr int Hc  = 8;
constexpr int Dc  = 32;
constexpr int SB  = 32;              // s rows per block
constexpr int TB  = 16;              // t cols per block
constexpr int NQ  = 8;               // 16B chunks per (s,h) row (32 floats)
constexpr int QROWS = SB * Hc;       // 256
constexpr int KROWS = TB * Hc;       // 128
constexpr int QST = QROWS + 1;       // 257 (16B units)
constexpr int KST = KROWS + 1;       // 129
constexpr int SMEM_U128 = NQ * QST + NQ * KST;   // 2056 + 1032 = 3088
}

__global__ void __launch_bounds__(256, 3)
l1attn_kernel(const float* __restrict__ qg_, const float* __restrict__ kg_,
              float* __restrict__ out) {
    extern __shared__ ulonglong2 sm[];
    ulonglong2* qs = sm;               // [NQ][QST]
    ulonglong2* ks = sm + NQ * QST;    // [NQ][KST]  (negated k)

    const int tid = threadIdx.x;
    const int b   = blockIdx.z;
    const int s0  = blockIdx.y * SB;
    const int t0  = blockIdx.x * TB;

    const float4* qg = reinterpret_cast<const float4*>(qg_ + (size_t)(b * Sc + s0) * Hc * Dc);
    const float4* kg = reinterpret_cast<const float4*>(kg_ + (size_t)(b * Sc + t0) * Hc * Dc);

    // Fill q tile: 2048 float4, 8/thread. g = row*8 + c -> transposed [c][row].
    #pragma unroll
    for (int i = 0; i < (QROWS * NQ) / 256; i++) {
        int g = tid + i * 256;
        int r = g >> 3;
        int c = g & 7;
        float4 v = qg[g];
        reinterpret_cast<float4&>(qs[c * QST + r]) = v;
    }
    // Fill k tile negated: 1024 float4, 4/thread.
    #pragma unroll
    for (int i = 0; i < (KROWS * NQ) / 256; i++) {
        int g = tid + i * 256;
        int r = g >> 3;
        int c = g & 7;
        float4 w = kg[g];
        w.x = -w.x; w.y = -w.y; w.z = -w.z; w.w = -w.w;
        reinterpret_cast<float4&>(ks[c * KST + r]) = w;
    }
    __syncthreads();

    // Mapping: h = tid&7, tq = (tid>>3)&3, warp sw = tid>>5 (0..7).
    // Thread tile: 4 s (sw + 8*ii) x 4 t (tq + 4*jj), fixed h.
    const int h  = tid & 7;
    const int tq = (tid >> 3) & 3;
    const int sw = tid >> 5;
    const int qoff = sw * 8 + h;     // + 64*ii   (row index < 256)
    const int koff = tq * 8 + h;     // + 32*jj   (row index < 128)

    unsigned long long acc[4][4];
    #pragma unroll
    for (int ii = 0; ii < 4; ii++)
        #pragma unroll
        for (int jj = 0; jj < 4; jj++)
            acc[ii][jj] = 0ull;

    #pragma unroll
    for (int c = 0; c < NQ; c++) {            // each c = 4 d's (2 packed pairs)
        const ulonglong2* qrow = qs + c * QST;
        const ulonglong2* krow = ks + c * KST;
        ulonglong2 q2[4], k2[4];
        #pragma unroll
        for (int ii = 0; ii < 4; ii++) q2[ii] = qrow[qoff + 64 * ii];
        #pragma unroll
        for (int jj = 0; jj < 4; jj++) k2[jj] = krow[koff + 32 * jj];

        #pragma unroll
        for (int ii = 0; ii < 4; ii++) {
            #pragma unroll
            for (int jj = 0; jj < 4; jj++) {
                unsigned long long d2, a;
                asm("add.rn.f32x2 %0, %1, %2;" : "=l"(d2) : "l"(q2[ii].x), "l"(k2[jj].x));
                d2 &= 0x7FFFFFFF7FFFFFFFULL;
                asm("add.rn.f32x2 %0, %1, %2;" : "=l"(a) : "l"(acc[ii][jj]), "l"(d2));
                acc[ii][jj] = a;
                asm("add.rn.f32x2 %0, %1, %2;" : "=l"(d2) : "l"(q2[ii].y), "l"(k2[jj].y));
                d2 &= 0x7FFFFFFF7FFFFFFFULL;
                asm("add.rn.f32x2 %0, %1, %2;" : "=l"(a) : "l"(acc[ii][jj]), "l"(d2));
                acc[ii][jj] = a;
            }
        }
    }

    // Epilogue: 16 STG.32; per (ii,jj) a warp covers 32 consecutive floats
    // over (t,h) -> 128B coalesced.
    const float nscale = -0.17677669529663687f;  // -1/sqrt(32)
    #pragma unroll
    for (int ii = 0; ii < 4; ii++) {
        int s = s0 + sw + 8 * ii;
        size_t rowbase = ((size_t)b * Sc + s) * (size_t)Sc;
        #pragma unroll
        for (int jj = 0; jj < 4; jj++) {
            int t = t0 + tq + 4 * jj;
            float2 a = reinterpret_cast<float2&>(acc[ii][jj]);
            out[(rowbase + t) * Hc + h] = (a.x + a.y) * nscale;
        }
    }
}

extern "C" void kernel_launch(void* const* d_in, const int* in_sizes, int n_in,
                              void* d_out, int out_size) {
    const float* q = (const float*)d_in[0];
    const float* k = (const float*)d_in[1];
    float* out = (float*)d_out;

    const int smem_bytes = SMEM_U128 * (int)sizeof(ulonglong2);  // 49408
    cudaFuncSetAttribute(l1attn_kernel,
                         cudaFuncAttributeMaxDynamicSharedMemorySize, smem_bytes);

    dim3 grid(Sc / TB, Sc / SB, Bc);   // (128, 64, 2)
    l1attn_kernel<<<grid, 256, smem_bytes>>>(q, k, out);
}

// round 7
// speedup vs baseline: 1.0701x; 1.0108x over previous
#include <cuda_runtime.h>
#include <cstdint>
#include <cstddef>

// L1 attention: out[b,s,t,h] = -(1/sqrt(D)) * sum_d |q[b,s,h,d] - k[b,t,h,d]|
// B=2, S=2048, H=8, D=32. Output [b,s,t,h].
//
// Inner unit per packed d-pair: add.rn.f32x2 (fma) + 64-bit AND (2x LOP3,
// alu) + add.rn.f32x2 (fma). -k in SMEM so diff is one packed add.
// Warp-instruction floor: 4 slots / 2 elements -> issue floor ~132us.
//
// R7: R2/R6 both stuck at issue=68.6% (lockstep LDS stalls at c-iteration
// heads). Fix: 4s x 8t per-thread tile (best issue:crossbar ratio), u128
// fringe loads, and MANUAL SOFTWARE PIPELINING: k fringe in halves, next
// half's loads issued between math chunks so every LDS has ~500 wall cycles
// of independent math covering its latency. 2 CTAs/SM, ~120 regs.

namespace {
constexpr int Bc  = 2;
constexpr int Sc  = 2048;
constexpr int Hc  = 8;
constexpr int Dc  = 32;
constexpr int SB  = 32;              // s rows per block
constexpr int TB  = 32;              // t cols per block
constexpr int NQ  = 8;               // 16B chunks per (s,h) row
constexpr int QROWS = SB * Hc;       // 256
constexpr int KROWS = TB * Hc;       // 256
constexpr int QST = QROWS + 1;       // 257 (16B units)
constexpr int KST = KROWS + 1;       // 257
constexpr int SMEM_U128 = NQ * QST + NQ * KST;   // 4112
}

__global__ void __launch_bounds__(256, 2)
l1attn_kernel(const float* __restrict__ qg_, const float* __restrict__ kg_,
              float* __restrict__ out) {
    extern __shared__ ulonglong2 sm[];
    ulonglong2* qs = sm;               // [NQ][QST]
    ulonglong2* ks = sm + NQ * QST;    // [NQ][KST]  (negated k)

    const int tid = threadIdx.x;
    const int b   = blockIdx.z;
    const int s0  = blockIdx.y * SB;
    const int t0  = blockIdx.x * TB;

    const float4* qg = reinterpret_cast<const float4*>(qg_ + (size_t)(b * Sc + s0) * Hc * Dc);
    const float4* kg = reinterpret_cast<const float4*>(kg_ + (size_t)(b * Sc + t0) * Hc * Dc);

    // Fill: 2048 float4 per tile, 8/thread each. g = row*8 + c -> [c][row].
    #pragma unroll
    for (int i = 0; i < (QROWS * NQ) / 256; i++) {
        int g = tid + i * 256;
        int r = g >> 3;
        int c = g & 7;
        float4 v = qg[g];
        reinterpret_cast<float4&>(qs[c * QST + r]) = v;
        float4 w = kg[g];
        w.x = -w.x; w.y = -w.y; w.z = -w.z; w.w = -w.w;
        reinterpret_cast<float4&>(ks[c * KST + r]) = w;
    }
    __syncthreads();

    // Mapping: h = tid&7, tq = (tid>>3)&3, warp sw = tid>>5.
    // Thread tile: 4 s (sw + 8*ii) x 8 t (tq + 4*jj), fixed h.
    const int h  = tid & 7;
    const int tq = (tid >> 3) & 3;
    const int sw = tid >> 5;
    const int qoff = sw * 8 + h;     // + 64*ii
    const int koff = tq * 8 + h;     // + 32*jj

    unsigned long long acc[4][8];
    #pragma unroll
    for (int ii = 0; ii < 4; ii++)
        #pragma unroll
        for (int jj = 0; jj < 8; jj++)
            acc[ii][jj] = 0ull;

    ulonglong2 q2[4], kh0[4], kh1[4];

    // One packed-pair unit: diff = q + (-k); abs; acc += abs.
#define L1_UNIT(QV, KV, AC)                                                  \
    do {                                                                     \
        unsigned long long d2_, a_;                                          \
        asm("add.rn.f32x2 %0, %1, %2;" : "=l"(d2_) : "l"(QV), "l"(KV));      \
        d2_ &= 0x7FFFFFFF7FFFFFFFULL;                                        \
        asm("add.rn.f32x2 %0, %1, %2;" : "=l"(a_) : "l"(AC), "l"(d2_));      \
        AC = a_;                                                             \
    } while (0)

#define L1_MATH(KH, JB)                                                      \
    do {                                                                     \
        _Pragma("unroll")                                                    \
        for (int ii = 0; ii < 4; ii++) {                                     \
            _Pragma("unroll")                                                \
            for (int j = 0; j < 4; j++) {                                    \
                L1_UNIT(q2[ii].x, KH[j].x, acc[ii][JB + j]);                 \
                L1_UNIT(q2[ii].y, KH[j].y, acc[ii][JB + j]);                 \
            }                                                                \
        }                                                                    \
    } while (0)

    // Preload k half0 for c = 0.
    #pragma unroll
    for (int j = 0; j < 4; j++) kh0[j] = ks[koff + 32 * j];

    #pragma unroll
    for (int c = 0; c < NQ; c++) {
        const ulonglong2* qrow = qs + c * QST;
        const ulonglong2* krow = ks + c * KST;
        #pragma unroll
        for (int ii = 0; ii < 4; ii++) q2[ii] = qrow[qoff + 64 * ii];
        #pragma unroll
        for (int j = 0; j < 4; j++) kh1[j] = krow[koff + 32 * (4 + j)];

        L1_MATH(kh0, 0);                     // kh0 was loaded long ago

        if (c < NQ - 1) {                    // prefetch next c's half0
            const ulonglong2* krn = krow + KST;
            #pragma unroll
            for (int j = 0; j < 4; j++) kh0[j] = krn[koff + 32 * j];
        }

        L1_MATH(kh1, 4);                     // covers kh0-prefetch latency
    }
#undef L1_MATH
#undef L1_UNIT

    // Epilogue: per (ii,jj) a warp covers 32 consecutive floats over (t,h).
    const float nscale = -0.17677669529663687f;  // -1/sqrt(32)
    #pragma unroll
    for (int ii = 0; ii < 4; ii++) {
        int s = s0 + sw + 8 * ii;
        size_t rowbase = ((size_t)b * Sc + s) * (size_t)Sc;
        #pragma unroll
        for (int jj = 0; jj < 8; jj++) {
            int t = t0 + tq + 4 * jj;
            float2 a = reinterpret_cast<float2&>(acc[ii][jj]);
            out[(rowbase + t) * Hc + h] = (a.x + a.y) * nscale;
        }
    }
}

extern "C" void kernel_launch(void* const* d_in, const int* in_sizes, int n_in,
                              void* d_out, int out_size) {
    const float* q = (const float*)d_in[0];
    const float* k = (const float*)d_in[1];
    float* out = (float*)d_out;

    const int smem_bytes = SMEM_U128 * (int)sizeof(ulonglong2);  // 65792
    cudaFuncSetAttribute(l1attn_kernel,
                         cudaFuncAttributeMaxDynamicSharedMemorySize, smem_bytes);

    dim3 grid(Sc / TB, Sc / SB, Bc);   // (64, 64, 2)
    l1attn_kernel<<<grid, 256, smem_bytes>>>(q, k, out);
}